// round 3
// baseline (speedup 1.0000x reference)
#include <cuda_runtime.h>
#include <cuda_bf16.h>
#include <cstdint>

// FreezedScaledFakeQuantize: out = (clip(round(X/s + zp), qmin, qmax) - zp) * s
// X: [8192, 8192] f32, scale/zp: [8192, 64] f32 (group size 128), qmin/qmax: int scalars.
// Memory-bound: ~516 MB traffic -> target ~85-110 us.

static constexpr int NGROUPS = 64;     // COLS / GROUP = 8192 / 128
static constexpr int LOG2_V4_PER_ROW = 11;   // 8192/4 = 2048 float4 per row

__global__ void __launch_bounds__(256)
fakequant_kernel(const float4* __restrict__ X,
                 const float* __restrict__ scale,
                 const float* __restrict__ zero_point,
                 const int* __restrict__ qmin_p,
                 const int* __restrict__ qmax_p,
                 float4* __restrict__ out,
                 unsigned int n_v4)
{
    const float qmin = (float)(*qmin_p);
    const float qmax = (float)(*qmax_p);

    const unsigned int stride = gridDim.x * blockDim.x;
    for (unsigned int i = blockIdx.x * blockDim.x + threadIdx.x; i < n_v4; i += stride) {
        const unsigned int row  = i >> LOG2_V4_PER_ROW;          // i / 2048
        const unsigned int c4   = i & ((1u << LOG2_V4_PER_ROW) - 1u);
        const unsigned int g    = c4 >> 5;                        // 32 float4s per group
        const unsigned int sidx = row * NGROUPS + g;

        const float s   = scale[sidx];
        const float zp  = zero_point[sidx];
        const float inv = 1.0f / s;           // precise div, amortized over 4 lanes

        const float4 x = X[i];

        float4 r; float q;
        q = rintf(fmaf(x.x, inv, zp)); q = fminf(fmaxf(q, qmin), qmax); r.x = (q - zp) * s;
        q = rintf(fmaf(x.y, inv, zp)); q = fminf(fmaxf(q, qmin), qmax); r.y = (q - zp) * s;
        q = rintf(fmaf(x.z, inv, zp)); q = fminf(fmaxf(q, qmin), qmax); r.z = (q - zp) * s;
        q = rintf(fmaf(x.w, inv, zp)); q = fminf(fmaxf(q, qmin), qmax); r.w = (q - zp) * s;

        out[i] = r;
    }
}

extern "C" void kernel_launch(void* const* d_in, const int* in_sizes, int n_in,
                              void* d_out, int out_size)
{
    const float4* X   = (const float4*)d_in[0];
    const float* s    = (const float*)d_in[1];
    const float* zp   = (const float*)d_in[2];
    const int*   qmin = (const int*)d_in[3];
    const int*   qmax = (const int*)d_in[4];
    float4*      out  = (float4*)d_out;

    const unsigned int n_v4 = (unsigned int)(in_sizes[0] / 4);   // 16,777,216
    const int threads = 256;
    const int blocks  = (int)((n_v4 + threads - 1) / threads);   // 65,536 at full size
    fakequant_kernel<<<blocks, threads>>>(X, s, zp, qmin, qmax, out, n_v4);
}

// round 4
// speedup vs baseline: 1.2894x; 1.2894x over previous
#include <cuda_runtime.h>
#include <cuda_bf16.h>
#include <cstdint>

// FreezedScaledFakeQuantize: out = (clip(round(X/s + zp), qmin, qmax) - zp) * s
// X: [8192, 8192] f32, scale/zp: [8192, 64] f32 (group 128), qmin/qmax int scalars.
// R3 evidence: DRAM 58.9%, issue 31.7% -> latency-bound at MLP=1.
// Fix: 4 float4s per thread, loads front-batched for MLP_eff ~= 4.

static constexpr int NGROUPS = 64;           // 8192 / 128
static constexpr int LOG2_V4_PER_ROW = 11;   // 2048 float4 per row
static constexpr int THREADS = 256;
static constexpr int UNROLL  = 4;            // float4s per thread

__global__ void __launch_bounds__(THREADS)
fakequant_kernel(const float4* __restrict__ X,
                 const float* __restrict__ scale,
                 const float* __restrict__ zero_point,
                 const int* __restrict__ qmin_p,
                 const int* __restrict__ qmax_p,
                 float4* __restrict__ out,
                 unsigned int n_v4)
{
    const float qmin = (float)(*qmin_p);
    const float qmax = (float)(*qmax_p);

    const unsigned int base = blockIdx.x * (THREADS * UNROLL) + threadIdx.x;

    unsigned int idx[UNROLL];
    float4 x[UNROLL];
    float  s[UNROLL], zp[UNROLL];
    bool   ok[UNROLL];

    // Front-batched loads: 4x LDG.128 + 8x LDG.32 issued before any compute.
    #pragma unroll
    for (int k = 0; k < UNROLL; k++) {
        idx[k] = base + k * THREADS;
        ok[k]  = idx[k] < n_v4;
        const unsigned int row  = idx[k] >> LOG2_V4_PER_ROW;
        const unsigned int c4   = idx[k] & ((1u << LOG2_V4_PER_ROW) - 1u);
        const unsigned int sidx = row * NGROUPS + (c4 >> 5);
        if (ok[k]) {
            x[k]  = X[idx[k]];
            s[k]  = scale[sidx];
            zp[k] = zero_point[sidx];
        }
    }

    #pragma unroll
    for (int k = 0; k < UNROLL; k++) {
        if (!ok[k]) continue;
        const float inv = 1.0f / s[k];
        float4 r; float q;
        q = rintf(fmaf(x[k].x, inv, zp[k])); q = fminf(fmaxf(q, qmin), qmax); r.x = (q - zp[k]) * s[k];
        q = rintf(fmaf(x[k].y, inv, zp[k])); q = fminf(fmaxf(q, qmin), qmax); r.y = (q - zp[k]) * s[k];
        q = rintf(fmaf(x[k].z, inv, zp[k])); q = fminf(fmaxf(q, qmin), qmax); r.z = (q - zp[k]) * s[k];
        q = rintf(fmaf(x[k].w, inv, zp[k])); q = fminf(fmaxf(q, qmin), qmax); r.w = (q - zp[k]) * s[k];
        out[idx[k]] = r;
    }
}

extern "C" void kernel_launch(void* const* d_in, const int* in_sizes, int n_in,
                              void* d_out, int out_size)
{
    const float4* X   = (const float4*)d_in[0];
    const float* s    = (const float*)d_in[1];
    const float* zp   = (const float*)d_in[2];
    const int*   qmin = (const int*)d_in[3];
    const int*   qmax = (const int*)d_in[4];
    float4*      out  = (float4*)d_out;

    const unsigned int n_v4 = (unsigned int)(in_sizes[0] / 4);      // 16,777,216
    const unsigned int per_block = THREADS * UNROLL;                // 1024 float4s
    const int blocks = (int)((n_v4 + per_block - 1) / per_block);   // 16,384
    fakequant_kernel<<<blocks, THREADS>>>(X, s, zp, qmin, qmax, out, n_v4);
}